// round 16
// baseline (speedup 1.0000x reference)
#include <cuda_runtime.h>
#include <stdint.h>

// SeqOperation_28106265985064 — FINAL, converged (5x reproduced:
// 123.4/123.3/123.2/123.1/123.0 us @ ~83% DRAM, 6.6 TB/s).
//
// Algebraic collapse of the reference (one-hot/roll/where chain) into a
// per-row gather, p = pos_idx[b] (int32 on device):
//   out[b,i,:] = seq[b,p,:]     if i == (p+1) % n          (ungated)
//              = seq[b,i,:]     if p<=n-3 && i < p
//              = seq[b,i-2,:]   if p<=n-3 && i >= p+3
//              = 0              otherwise
// seq: (B=4096, n=200, d=128) f32. ~830 MB minimal traffic (read once + write).
//
// Lever matrix (all measured, session R3-R15):
//   MLP 1->2 front-batched loads : WIN  145.8 -> 123.4us, DRAM 69.8 -> 83.2%
//   MLP 2->4                     : flat (latency fully hidden at MLP=2)
//   __ldcs/__stcs streaming      : flat (cache policy non-binding)
//   512-thread blocks            : flat (occupancy non-binding)
//   persistent grid-stride       : REGRESSION +10% (flat launch's cross-CTA
//                                  MLP + dense per-wave locality wins)
// Closed channels: traffic at logical floor; LTS cap path-independent on B300
// (TMA == LDG); no SM-side constraint (issue 24%, pipes <18%). This is the
// achieved HBM mixed-R/W roofline for this access pattern.

constexpr int N_SEQ = 200;
constexpr int D4    = 32;            // d=128 floats = 32 float4 per row
constexpr int ROWS_PER_WARP   = 2;
constexpr int WARPS_PER_BLOCK = 8;   // 256 threads
constexpr int ROWS_PER_BLOCK  = ROWS_PER_WARP * WARPS_PER_BLOCK;  // 16

__device__ __forceinline__ int src_row(int i, int p)
{
    // source row within batch, or -1 for zero-fill
    bool valid = (p <= N_SEQ - 3);
    int pp1 = (p + 1 == N_SEQ) ? 0 : (p + 1);
    if (i == pp1) return p;                    // rolled "pos" term, NOT gated
    if (valid) {
        if (i < p)      return i;              // left term
        if (i >= p + 3) return i - 2;          // rolled "right" term
    }
    return -1;
}

__global__ __launch_bounds__(256)
void seqop_kernel(const float4* __restrict__ seq,
                  const int* __restrict__ pos_idx,
                  float4* __restrict__ out,
                  int total_rows)
{
    int warp = blockIdx.x * WARPS_PER_BLOCK + (threadIdx.x >> 5);
    int lane = threadIdx.x & 31;
    int r0   = warp * ROWS_PER_WARP;
    if (r0 >= total_rows) return;

    int src[ROWS_PER_WARP];

    #pragma unroll
    for (int k = 0; k < ROWS_PER_WARP; k++) {
        int r = r0 + k;
        int b = r / N_SEQ;
        int i = r - b * N_SEQ;
        int p = __ldg(&pos_idx[b]);
        src[k] = src_row(i, p);
        if (src[k] >= 0) src[k] += b * N_SEQ;  // absolute source row
    }

    // Front-batch loads so both LDG.128 are concurrently in flight (MLP=2).
    float4 v[ROWS_PER_WARP];
    #pragma unroll
    for (int k = 0; k < ROWS_PER_WARP; k++) {
        v[k] = make_float4(0.f, 0.f, 0.f, 0.f);
        if (src[k] >= 0)
            v[k] = __ldg(&seq[src[k] * D4 + lane]);
    }

    #pragma unroll
    for (int k = 0; k < ROWS_PER_WARP; k++) {
        out[(r0 + k) * D4 + lane] = v[k];      // always write: d_out poisoned
    }
}

extern "C" void kernel_launch(void* const* d_in, const int* in_sizes, int n_in,
                              void* d_out, int out_size)
{
    const float4* seq = (const float4*)d_in[0];
    const int*    pos = (const int*)d_in[1];
    float4*       o   = (float4*)d_out;

    int B = in_sizes[1];                 // 4096
    int total_rows = B * N_SEQ;          // 819200

    int grid = (total_rows + ROWS_PER_BLOCK - 1) / ROWS_PER_BLOCK;  // 51200
    seqop_kernel<<<grid, 256>>>(seq, pos, o, total_rows);
}

// round 17
// speedup vs baseline: 1.0062x; 1.0062x over previous
#include <cuda_runtime.h>
#include <stdint.h>

// SeqOperation_28106265985064 — FINAL, converged (6x reproduced:
// 123.4/123.3/123.2/123.1/123.0/123.7 us @ ~83% DRAM, 6.6 TB/s; residual
// spread is harness jitter — ncu kernel time and DRAM% are stable).
//
// Algebraic collapse of the reference (one-hot/roll/where chain) into a
// per-row gather, p = pos_idx[b] (int32 on device):
//   out[b,i,:] = seq[b,p,:]     if i == (p+1) % n          (ungated)
//              = seq[b,i,:]     if p<=n-3 && i < p
//              = seq[b,i-2,:]   if p<=n-3 && i >= p+3
//              = 0              otherwise
// seq: (B=4096, n=200, d=128) f32. ~830 MB minimal traffic (read once + write).
//
// Lever matrix (all measured, session R3-R16):
//   MLP 1->2 front-batched loads : WIN  145.8 -> 123.4us, DRAM 69.8 -> 83.2%
//   MLP 2->4                     : flat (latency fully hidden at MLP=2)
//   __ldcs/__stcs streaming      : flat (cache policy non-binding)
//   512-thread blocks            : flat (occupancy non-binding)
//   persistent grid-stride       : REGRESSION +10% (flat launch's cross-CTA
//                                  MLP + dense per-wave locality wins)
// Closed channels: traffic at logical floor; LTS cap path-independent on B300
// (TMA == LDG); no SM-side constraint (issue 24%, pipes <18%). This is the
// achieved HBM mixed-R/W roofline for this access pattern.

constexpr int N_SEQ = 200;
constexpr int D4    = 32;            // d=128 floats = 32 float4 per row
constexpr int ROWS_PER_WARP   = 2;
constexpr int WARPS_PER_BLOCK = 8;   // 256 threads
constexpr int ROWS_PER_BLOCK  = ROWS_PER_WARP * WARPS_PER_BLOCK;  // 16

__device__ __forceinline__ int src_row(int i, int p)
{
    // source row within batch, or -1 for zero-fill
    bool valid = (p <= N_SEQ - 3);
    int pp1 = (p + 1 == N_SEQ) ? 0 : (p + 1);
    if (i == pp1) return p;                    // rolled "pos" term, NOT gated
    if (valid) {
        if (i < p)      return i;              // left term
        if (i >= p + 3) return i - 2;          // rolled "right" term
    }
    return -1;
}

__global__ __launch_bounds__(256)
void seqop_kernel(const float4* __restrict__ seq,
                  const int* __restrict__ pos_idx,
                  float4* __restrict__ out,
                  int total_rows)
{
    int warp = blockIdx.x * WARPS_PER_BLOCK + (threadIdx.x >> 5);
    int lane = threadIdx.x & 31;
    int r0   = warp * ROWS_PER_WARP;
    if (r0 >= total_rows) return;

    int src[ROWS_PER_WARP];

    #pragma unroll
    for (int k = 0; k < ROWS_PER_WARP; k++) {
        int r = r0 + k;
        int b = r / N_SEQ;
        int i = r - b * N_SEQ;
        int p = __ldg(&pos_idx[b]);
        src[k] = src_row(i, p);
        if (src[k] >= 0) src[k] += b * N_SEQ;  // absolute source row
    }

    // Front-batch loads so both LDG.128 are concurrently in flight (MLP=2).
    float4 v[ROWS_PER_WARP];
    #pragma unroll
    for (int k = 0; k < ROWS_PER_WARP; k++) {
        v[k] = make_float4(0.f, 0.f, 0.f, 0.f);
        if (src[k] >= 0)
            v[k] = __ldg(&seq[src[k] * D4 + lane]);
    }

    #pragma unroll
    for (int k = 0; k < ROWS_PER_WARP; k++) {
        out[(r0 + k) * D4 + lane] = v[k];      // always write: d_out poisoned
    }
}

extern "C" void kernel_launch(void* const* d_in, const int* in_sizes, int n_in,
                              void* d_out, int out_size)
{
    const float4* seq = (const float4*)d_in[0];
    const int*    pos = (const int*)d_in[1];
    float4*       o   = (float4*)d_out;

    int B = in_sizes[1];                 // 4096
    int total_rows = B * N_SEQ;          // 819200

    int grid = (total_rows + ROWS_PER_BLOCK - 1) / ROWS_PER_BLOCK;  // 51200
    seqop_kernel<<<grid, 256>>>(seq, pos, o, total_rows);
}